// round 14
// baseline (speedup 1.0000x reference)
#include <cuda_runtime.h>
#include <cuda_fp16.h>

#define NN 25000
#define NE 400000
#define EE (NE + NN)          // 425000 (edges + self loops)
#define SC 0.35355339059327378f   // 1/sqrt(8)

// ---------------- scratch (static __device__, no allocs) ----------------
__device__ float2   g_x0[NN * 32];   // layer-0 h, pair layout (lane l = dims 2l,2l+1)
__device__ float2   g_x1[NN * 32];   // layer-1 out (pair layout)
__device__ float2   g_QA[NN * 32];   // Q after layer1 (pre-scaled by SC)
__device__ float2   g_QB[NN * 32];   // Q after layer2
__device__ unsigned g_V1[NN * 32];   // layer-0 V half2 (unscaled until k_scatter applies dis)
__device__ uint4    g_KVA[NN * 32];  // {K_l0, V_l0*dis, K_l1, V_l1*dis} (layer-1 weights)
__device__ uint4    g_KVB[NN * 32];  // {K_l0, V_l0*dis, K_l1, V_l1*dis} (layer-2 weights)
__device__ uint2    g_KVc[NN * 32];  // {K_l2, V_l2*dis} (layer-2 weights)
__device__ float    g_dis[NN];
__device__ int      g_deg[NN];       // invariant: all-zero at kernel_launch entry
__device__ int      g_off[NN + 1];
__device__ int      g_cur[NN];
__device__ int4     g_csr4[(EE + 3) / 4 + 1];   // csr as int4 for aligned 16B uniform loads

__device__ __forceinline__ float2 u2f(unsigned u) {
    return __half22float2(*reinterpret_cast<const __half2*>(&u));
}
__device__ __forceinline__ unsigned f2u(float x, float y) {
    __half2 h = __floats2half2_rn(x, y);
    return *reinterpret_cast<unsigned*>(&h);
}

#define CP_ASYNC16(dst, src) \
    asm volatile("cp.async.cg.shared.global [%0], [%1], 16;" :: "r"(dst), "l"(src))
#define CP_COMMIT() asm volatile("cp.async.commit_group;")
#define CP_WAIT1()  asm volatile("cp.async.wait_group 1;")

// ---------------- CSR build ----------------
// single-block scan over NN elements; also computes dis, seeds cur, resets deg
__global__ void k_scan() {
    __shared__ int wsum[32];
    int t = threadIdx.x;
    int lane = t & 31, wid = t >> 5;
    int i0 = t * 25;
    int i1 = i0 + 25 < NN ? i0 + 25 : NN;
    int s = 0;
    for (int i = i0; i < i1; i++) s += g_deg[i] + 1;   // +1 = self loop
    int inc = s;
#pragma unroll
    for (int o = 1; o < 32; o <<= 1) {
        int v = __shfl_up_sync(0xffffffffu, inc, o);
        if (lane >= o) inc += v;
    }
    if (lane == 31) wsum[wid] = inc;
    __syncthreads();
    if (t < 32) {
        int v = wsum[t];
        int inc2 = v;
#pragma unroll
        for (int o = 1; o < 32; o <<= 1) {
            int u = __shfl_up_sync(0xffffffffu, inc2, o);
            if (t >= o) inc2 += u;
        }
        wsum[t] = inc2 - v;   // exclusive
    }
    __syncthreads();
    int run = wsum[wid] + (inc - s);
    for (int i = i0; i < i1; i++) {
        int d = g_deg[i] + 1;
        g_off[i] = run;
        g_cur[i] = run;
        g_dis[i] = rsqrtf((float)d);
        g_deg[i] = 0;          // restore invariant for next replay
        run += d;
    }
    if (t == 0) g_off[NN] = EE;
}

// scatter + in-place V1 scaling by dis (dis is ready; V1 was written by lin1)
__global__ void k_scatter(const int* __restrict__ ei) {
    int idx = blockIdx.x * blockDim.x + threadIdx.x;
    int stride = gridDim.x * blockDim.x;
    for (int i = idx; i < NN * 32; i += stride) {
        float d = g_dis[i >> 5];
        float2 f = u2f(g_V1[i]);
        g_V1[i] = f2u(f.x * d, f.y * d);
    }
    if (idx >= EE) return;
    int r, c;
    if (idx < NE) { r = ei[idx]; c = ei[NE + idx]; }
    else          { r = c = idx - NE; }               // self loop
    int p = atomicAdd(&g_cur[c], 1);
    ((int*)g_csr4)[p] = r;
}

// ---------------- helpers ----------------
__device__ __forceinline__ void gather_pair(float2 h, int g0, float (&xa)[8]) {
#pragma unroll
    for (int i = 0; i < 8; i += 2) {
        int src = g0 * 4 + (i >> 1);
        xa[i]     = __shfl_sync(0xffffffffu, h.x, src);
        xa[i + 1] = __shfl_sync(0xffffffffu, h.y, src);
    }
}

__device__ __forceinline__ void load_w_padded(const float* __restrict__ w, float2* sw) {
    for (int i = threadIdx.x; i < 256; i += blockDim.x) {
        int g = i >> 5, r = i & 31;
        sw[g * 33 + r] = ((const float2*)w)[i];
    }
}

__device__ __forceinline__ float2 glin(const float2* sw, const float* sb,
                                       const float (&xa)[8], int wbase, int lane) {
    float2 o = ((const float2*)sb)[lane];
#pragma unroll
    for (int i = 0; i < 8; i++) {
        float2 w = sw[wbase + i * 4];
        o.x += xa[i] * w.x;
        o.y += xa[i] * w.y;
    }
    return o;
}

// ---------------- fused edge-histogram + lin1 (cp.async, 16 nodes/warp) + qkv1 ----------------
// block = 128 thr = 4 warps, 64 nodes/block (16 per warp); lane = out pair {2l,2l+1}
__global__ void k_lin1histqkv1(const float* __restrict__ x, const float* __restrict__ w,
                               const float* __restrict__ b,
                               const float* __restrict__ wv0, const float* __restrict__ bv0,
                               const int* __restrict__ ei) {
    __shared__ float4 sx[2][64][16];   // double buffer: 2 x 64 nodes x 64 k (16 float4)
    __shared__ float2 swv[264];
    __shared__ float sbv[64];
    int t = threadIdx.x;

    // edge histogram (independent work; atomics drain during the GEMM below)
    {
        int stride = gridDim.x * blockDim.x;
        for (int e = blockIdx.x * blockDim.x + t; e < NE; e += stride)
            atomicAdd(&g_deg[ei[NE + e]], 1);
    }

    load_w_padded(wv0, swv);
    if (t < 64) sbv[t] = bv0[t];
    int warp = t >> 5, lane = t & 31;
    int nodeBase = blockIdx.x * 64;
    const float4* __restrict__ X4 = (const float4*)x;
    const float2* __restrict__ W2 = (const float2*)w;

    // staging geometry: 2 threads per row, 8 consecutive float4 per thread
    int srow = t >> 1;
    int scol = (t & 1) * 8;
    int node_s = nodeBase + srow;
    const float4* __restrict__ Xs = X4 + (size_t)node_s * 64 + scol;
    bool ld_ok = (node_s < NN);

#pragma unroll
    for (int tl = 0; tl < 2; tl++) {
        if (ld_ok) {
#pragma unroll
            for (int i = 0; i < 8; i++) {
                unsigned dst = (unsigned)__cvta_generic_to_shared(&sx[tl][srow][scol + i]);
                CP_ASYNC16(dst, Xs + tl * 16 + i);
            }
        }
        CP_COMMIT();
    }

    float2 acc[16];
#pragma unroll
    for (int n = 0; n < 16; n++) acc[n] = make_float2(0.f, 0.f);

#pragma unroll
    for (int tile = 0; tile < 4; tile++) {
        CP_WAIT1();
        __syncthreads();
        int buf = tile & 1;
        int k0 = tile * 64;
#pragma unroll 2
        for (int ks = 0; ks < 16; ks++) {
            int kw = (k0 + ks * 4) * 32 + lane;
            float2 w0 = W2[kw];
            float2 w1 = W2[kw + 32];
            float2 w2v = W2[kw + 64];
            float2 w3 = W2[kw + 96];
#pragma unroll
            for (int n = 0; n < 16; n++) {
                float4 xv = sx[buf][warp * 16 + n][ks];
                acc[n].x = fmaf(xv.x, w0.x, fmaf(xv.y, w1.x,
                           fmaf(xv.z, w2v.x, fmaf(xv.w, w3.x, acc[n].x))));
                acc[n].y = fmaf(xv.x, w0.y, fmaf(xv.y, w1.y,
                           fmaf(xv.z, w2v.y, fmaf(xv.w, w3.y, acc[n].y))));
            }
        }
        __syncthreads();
        if (tile + 2 < 4 && ld_ok) {
#pragma unroll
            for (int i = 0; i < 8; i++) {
                unsigned dst = (unsigned)__cvta_generic_to_shared(&sx[buf][srow][scol + i]);
                CP_ASYNC16(dst, Xs + (tile + 2) * 16 + i);
            }
        }
        CP_COMMIT();
    }

    float2 bb = ((const float2*)b)[lane];
    int g0 = lane >> 2;
    int wbase = g0 * 33 + (lane & 3);
#pragma unroll
    for (int n = 0; n < 16; n++) {
        int node = nodeBase + warp * 16 + n;
        float2 h = make_float2(fmaxf(acc[n].x + bb.x, 0.f), fmaxf(acc[n].y + bb.y, 0.f));
        float xa[8];
        gather_pair(h, g0, xa);           // all lanes participate (no divergence)
        float2 vv = glin(swv, sbv, xa, wbase, lane);
        if (node < NN) {
            g_x0[node * 32 + lane] = h;
            g_V1[node * 32 + lane] = f2u(vv.x, vv.y);   // unscaled; k_scatter applies dis
        }
    }
}

// ---------------- fused edge1 (identity attention) + qkv2 ----------------
__global__ void k_edge1qkv2(const float* __restrict__ wq, const float* __restrict__ bq,
                            const float* __restrict__ wk, const float* __restrict__ bk,
                            const float* __restrict__ wv, const float* __restrict__ bv) {
    __shared__ float2 swq[264], swk[264], swv[264];
    __shared__ float sbq[64], sbk[64], sbv[64];
    load_w_padded(wq, swq);
    load_w_padded(wk, swk);
    load_w_padded(wv, swv);
    if (threadIdx.x < 64) {
        sbq[threadIdx.x] = bq[threadIdx.x];
        sbk[threadIdx.x] = bk[threadIdx.x];
        sbv[threadIdx.x] = bv[threadIdx.x];
    }
    __syncthreads();
    int c = (blockIdx.x * blockDim.x + threadIdx.x) >> 5;
    if (c >= NN) return;
    int lane = threadIdx.x & 31;
    float ax = 0.f, ay = 0.f;
    int j = g_off[c], end = g_off[c + 1];
    const unsigned* __restrict__ V1 = g_V1;
    const int* __restrict__ csr = (const int*)g_csr4;
    // align j to 4 for int4 batches
    for (; j < end && (j & 3); j++) {
        float2 f = u2f(V1[csr[j] * 32 + lane]);
        ax += f.x;  ay += f.y;
    }
    // 8-wide batches (2 uniform int4 loads, 8 gathers in flight)
    for (; j + 8 <= end; j += 8) {
        int4 ra = g_csr4[j >> 2];
        int4 rb = g_csr4[(j >> 2) + 1];
        unsigned u0 = V1[ra.x * 32 + lane];
        unsigned u1 = V1[ra.y * 32 + lane];
        unsigned u2 = V1[ra.z * 32 + lane];
        unsigned u3 = V1[ra.w * 32 + lane];
        unsigned u4 = V1[rb.x * 32 + lane];
        unsigned u5 = V1[rb.y * 32 + lane];
        unsigned u6 = V1[rb.z * 32 + lane];
        unsigned u7 = V1[rb.w * 32 + lane];
        float2 f0 = u2f(u0), f1 = u2f(u1), f2 = u2f(u2), f3 = u2f(u3);
        float2 f4 = u2f(u4), f5 = u2f(u5), f6 = u2f(u6), f7 = u2f(u7);
        ax += ((f0.x + f1.x) + (f2.x + f3.x)) + ((f4.x + f5.x) + (f6.x + f7.x));
        ay += ((f0.y + f1.y) + (f2.y + f3.y)) + ((f4.y + f5.y) + (f6.y + f7.y));
    }
    if (j + 4 <= end) {
        int4 rr = g_csr4[j >> 2];
        unsigned u0 = V1[rr.x * 32 + lane];
        unsigned u1 = V1[rr.y * 32 + lane];
        unsigned u2 = V1[rr.z * 32 + lane];
        unsigned u3 = V1[rr.w * 32 + lane];
        float2 f0 = u2f(u0), f1 = u2f(u1), f2 = u2f(u2), f3 = u2f(u3);
        ax += (f0.x + f1.x) + (f2.x + f3.x);
        ay += (f0.y + f1.y) + (f2.y + f3.y);
        j += 4;
    }
    for (; j < end; j++) {
        float2 f = u2f(V1[csr[j] * 32 + lane]);
        ax += f.x;  ay += f.y;
    }
    float dc = g_dis[c];
    float2 h1 = make_float2(fmaxf(ax * dc, 0.f), fmaxf(ay * dc, 0.f));
    g_x1[c * 32 + lane] = h1;

    // qkv2: layers {0,1} K,V + Q(layer1), with net-layer-1 weights
    int g0 = lane >> 2;
    int wbase = g0 * 33 + (lane & 3);
    float2 h0 = g_x0[c * 32 + lane];
    float xa[8];
    uint4 pack;
    gather_pair(h0, g0, xa);
    {
        float2 kk = glin(swk, sbk, xa, wbase, lane);
        float2 vv = glin(swv, sbv, xa, wbase, lane);
        pack.x = f2u(kk.x, kk.y);
        pack.y = f2u(vv.x * dc, vv.y * dc);
    }
    gather_pair(h1, g0, xa);
    {
        float2 kk = glin(swk, sbk, xa, wbase, lane);
        float2 vv = glin(swv, sbv, xa, wbase, lane);
        float2 qq = glin(swq, sbq, xa, wbase, lane);
        pack.z = f2u(kk.x, kk.y);
        pack.w = f2u(vv.x * dc, vv.y * dc);
        g_QA[c * 32 + lane] = make_float2(qq.x * SC, qq.y * SC);
    }
    g_KVA[c * 32 + lane] = pack;
}

// ---------------- attention accumulators ----------------
__device__ __forceinline__ void acc2(uint4 d, float2 qv, float& ax, float& ay) {
    float2 k0 = u2f(d.x), v0 = u2f(d.y), k1 = u2f(d.z), v1 = u2f(d.w);
    float s0 = qv.x * k0.x + qv.y * k0.y;
    s0 += __shfl_xor_sync(0xffffffffu, s0, 1);
    s0 += __shfl_xor_sync(0xffffffffu, s0, 2);
    float s1 = qv.x * k1.x + qv.y * k1.y;
    s1 += __shfl_xor_sync(0xffffffffu, s1, 1);
    s1 += __shfl_xor_sync(0xffffffffu, s1, 2);
    float m = fmaxf(s0, s1);
    float e0 = __expf(s0 - m), e1 = __expf(s1 - m);
    float inv = __fdividef(1.0f, e0 + e1);
    ax += (e0 * v0.x + e1 * v1.x) * inv;
    ay += (e0 * v0.y + e1 * v1.y) * inv;
}

__device__ __forceinline__ void acc3(uint4 d, uint2 e, float2 qv, float& ax, float& ay) {
    float2 k0 = u2f(d.x), v0 = u2f(d.y), k1 = u2f(d.z), v1 = u2f(d.w);
    float2 k2 = u2f(e.x), v2 = u2f(e.y);
    float s0 = qv.x * k0.x + qv.y * k0.y;
    s0 += __shfl_xor_sync(0xffffffffu, s0, 1);
    s0 += __shfl_xor_sync(0xffffffffu, s0, 2);
    float s1 = qv.x * k1.x + qv.y * k1.y;
    s1 += __shfl_xor_sync(0xffffffffu, s1, 1);
    s1 += __shfl_xor_sync(0xffffffffu, s1, 2);
    float s2 = qv.x * k2.x + qv.y * k2.y;
    s2 += __shfl_xor_sync(0xffffffffu, s2, 1);
    s2 += __shfl_xor_sync(0xffffffffu, s2, 2);
    float m = fmaxf(fmaxf(s0, s1), s2);
    float e0 = __expf(s0 - m), e1 = __expf(s1 - m), e2 = __expf(s2 - m);
    float inv = __fdividef(1.0f, e0 + e1 + e2);
    ax += (e0 * v0.x + e1 * v1.x + e2 * v2.x) * inv;
    ay += (e0 * v0.y + e1 * v1.y + e2 * v2.y) * inv;
}

// ---------------- fused edge2 + qkv3 ----------------
__global__ void k_edge2qkv3(const float* __restrict__ wq, const float* __restrict__ bq,
                            const float* __restrict__ wk, const float* __restrict__ bk,
                            const float* __restrict__ wv, const float* __restrict__ bv) {
    __shared__ float2 swq[264], swk[264], swv[264];
    __shared__ float sbq[64], sbk[64], sbv[64];
    load_w_padded(wq, swq);
    load_w_padded(wk, swk);
    load_w_padded(wv, swv);
    if (threadIdx.x < 64) {
        sbq[threadIdx.x] = bq[threadIdx.x];
        sbk[threadIdx.x] = bk[threadIdx.x];
        sbv[threadIdx.x] = bv[threadIdx.x];
    }
    __syncthreads();
    int c = (blockIdx.x * blockDim.x + threadIdx.x) >> 5;
    if (c >= NN) return;
    int lane = threadIdx.x & 31;
    float2 qv = g_QA[c * 32 + lane];
    float ax = 0.f, ay = 0.f;
    int j = g_off[c], end = g_off[c + 1];
    const uint4* __restrict__ KV = g_KVA;
    const int* __restrict__ csr = (const int*)g_csr4;
    for (; j < end && (j & 3); j++)
        acc2(KV[csr[j] * 32 + lane], qv, ax, ay);
    for (; j + 4 <= end; j += 4) {
        int4 rr = g_csr4[j >> 2];
        uint4 d0 = KV[rr.x * 32 + lane];
        uint4 d1 = KV[rr.y * 32 + lane];
        uint4 d2 = KV[rr.z * 32 + lane];
        uint4 d3 = KV[rr.w * 32 + lane];
        acc2(d0, qv, ax, ay);
        acc2(d1, qv, ax, ay);
        acc2(d2, qv, ax, ay);
        acc2(d3, qv, ax, ay);
    }
    for (; j < end; j++)
        acc2(KV[csr[j] * 32 + lane], qv, ax, ay);

    float dc = g_dis[c];
    float2 h2 = make_float2(fmaxf(ax * dc, 0.f), fmaxf(ay * dc, 0.f));

    // qkv3: layers {0,1,2} K,V + Q(layer2), with net-layer-2 weights
    int g0 = lane >> 2;
    int wbase = g0 * 33 + (lane & 3);
    float xa[8];
    uint4 packA;
    gather_pair(g_x0[c * 32 + lane], g0, xa);
    {
        float2 kk = glin(swk, sbk, xa, wbase, lane);
        float2 vv = glin(swv, sbv, xa, wbase, lane);
        packA.x = f2u(kk.x, kk.y);
        packA.y = f2u(vv.x * dc, vv.y * dc);
    }
    gather_pair(g_x1[c * 32 + lane], g0, xa);
    {
        float2 kk = glin(swk, sbk, xa, wbase, lane);
        float2 vv = glin(swv, sbv, xa, wbase, lane);
        packA.z = f2u(kk.x, kk.y);
        packA.w = f2u(vv.x * dc, vv.y * dc);
    }
    g_KVB[c * 32 + lane] = packA;
    gather_pair(h2, g0, xa);
    {
        float2 kk = glin(swk, sbk, xa, wbase, lane);
        float2 vv = glin(swv, sbv, xa, wbase, lane);
        float2 qq = glin(swq, sbq, xa, wbase, lane);
        g_KVc[c * 32 + lane] = make_uint2(f2u(kk.x, kk.y), f2u(vv.x * dc, vv.y * dc));
        g_QB[c * 32 + lane] = make_float2(qq.x * SC, qq.y * SC);
    }
}

// ---------------- fused edge3 + lin2 + log_softmax ----------------
__global__ void k_edge3lin2(const float* __restrict__ w, const float* __restrict__ b,
                            float* __restrict__ out) {
    __shared__ float sw[2048];   // [64][32]
    __shared__ float sb[32];
    for (int i = threadIdx.x; i < 2048; i += blockDim.x) sw[i] = w[i];
    if (threadIdx.x < 32) sb[threadIdx.x] = b[threadIdx.x];
    __syncthreads();
    int c = (blockIdx.x * blockDim.x + threadIdx.x) >> 5;
    if (c >= NN) return;
    int lane = threadIdx.x & 31;
    float2 qv = g_QB[c * 32 + lane];
    float ax = 0.f, ay = 0.f;
    int j = g_off[c], end = g_off[c + 1];
    const uint4* __restrict__ KVa = g_KVB;
    const uint2* __restrict__ KVc = g_KVc;
    const int* __restrict__ csr = (const int*)g_csr4;
    for (; j < end && (j & 3); j++) {
        int r = csr[j];
        acc3(KVa[r * 32 + lane], KVc[r * 32 + lane], qv, ax, ay);
    }
    for (; j + 4 <= end; j += 4) {
        int4 rr = g_csr4[j >> 2];
        uint4 d0 = KVa[rr.x * 32 + lane];
        uint4 d1 = KVa[rr.y * 32 + lane];
        uint4 d2 = KVa[rr.z * 32 + lane];
        uint4 d3 = KVa[rr.w * 32 + lane];
        uint2 e0 = KVc[rr.x * 32 + lane];
        uint2 e1 = KVc[rr.y * 32 + lane];
        uint2 e2 = KVc[rr.z * 32 + lane];
        uint2 e3 = KVc[rr.w * 32 + lane];
        acc3(d0, e0, qv, ax, ay);
        acc3(d1, e1, qv, ax, ay);
        acc3(d2, e2, qv, ax, ay);
        acc3(d3, e3, qv, ax, ay);
    }
    for (; j < end; j++) {
        int r = csr[j];
        acc3(KVa[r * 32 + lane], KVc[r * 32 + lane], qv, ax, ay);
    }
    float dc = g_dis[c];
    float hx = fmaxf(ax * dc, 0.f), hy = fmaxf(ay * dc, 0.f);

    // lin2: lane = class; h dims {2lp, 2lp+1} live in lane lp
    float acc = sb[lane];
#pragma unroll
    for (int lp = 0; lp < 32; lp++) {
        float bx = __shfl_sync(0xffffffffu, hx, lp);
        float by = __shfl_sync(0xffffffffu, hy, lp);
        acc += bx * sw[(2 * lp) * 32 + lane] + by * sw[(2 * lp + 1) * 32 + lane];
    }
    float m = acc;
#pragma unroll
    for (int o = 16; o; o >>= 1) m = fmaxf(m, __shfl_xor_sync(0xffffffffu, m, o));
    float e = __expf(acc - m);
    float sum = e;
#pragma unroll
    for (int o = 16; o; o >>= 1) sum += __shfl_xor_sync(0xffffffffu, sum, o);
    out[(size_t)c * 32 + lane] = acc - m - logf(sum);
}

// ---------------- launch ----------------
extern "C" void kernel_launch(void* const* d_in, const int* in_sizes, int n_in,
                              void* d_out, int out_size) {
    const float* x  = (const float*)d_in[0];
    const int*   ei = (const int*)d_in[1];
    const float* w1 = (const float*)d_in[2];
    const float* b1 = (const float*)d_in[3];
    const float* wq = (const float*)d_in[4];
    const float* bq = (const float*)d_in[5];
    const float* wk = (const float*)d_in[6];
    const float* bk = (const float*)d_in[7];
    const float* wv = (const float*)d_in[8];
    const float* bv = (const float*)d_in[9];
    const float* w2 = (const float*)d_in[10];
    const float* b2 = (const float*)d_in[11];
    float* out = (float*)d_out;

    const int gridW = (NN * 32 + 255) / 256;   // warp-per-node kernels
    const int gridT = (NN + 63) / 64;          // 64 nodes per block for lin1 (128 thr)

    // launch 0: encoder + layer-0 V + edge histogram (fused, 16 nodes/warp)
    k_lin1histqkv1<<<gridT, 128>>>(x, w1, b1, wv, bv, ei);
    // launch 1: CSR offsets (+dis)
    k_scan<<<1, 1024>>>();
    // launch 2: scatter + V1 *= dis
    k_scatter<<<(EE + 255) / 256, 256>>>(ei);

    // launch 3: layer-0 edge + qkv for layer 1   <- 4th launch: ncu target
    k_edge1qkv2<<<gridW, 256>>>(wq + 512, bq + 64, wk + 512, bk + 64, wv + 512, bv + 64);
    // launch 4: layer-1 edge + qkv for layer 2
    k_edge2qkv3<<<gridW, 256>>>(wq + 1024, bq + 128, wk + 1024, bk + 128, wv + 1024, bv + 128);
    // launch 5: layer-2 edge + classifier
    k_edge3lin2<<<gridW, 256>>>(w2, b2, out);
}

// round 15
// speedup vs baseline: 1.0574x; 1.0574x over previous
#include <cuda_runtime.h>
#include <cuda_fp16.h>

#define NN 25000
#define NE 400000
#define EE (NE + NN)          // 425000 (edges + self loops)
#define SC 0.35355339059327378f   // 1/sqrt(8)

// ---------------- scratch (static __device__, no allocs) ----------------
__device__ float2   g_x0[NN * 32];   // layer-0 h, pair layout (lane l = dims 2l,2l+1)
__device__ float2   g_x1[NN * 32];   // layer-1 out (pair layout)
__device__ float2   g_QA[NN * 32];   // Q after layer1 (pre-scaled by SC)
__device__ float2   g_QB[NN * 32];   // Q after layer2
__device__ unsigned g_V1[NN * 32];   // layer-0 V half2 (unscaled until k_scatter applies dis)
__device__ uint4    g_KVA[NN * 32];  // {K_l0, V_l0*dis, K_l1, V_l1*dis} (layer-1 weights)
__device__ uint4    g_KVB[NN * 32];  // {K_l0, V_l0*dis, K_l1, V_l1*dis} (layer-2 weights)
__device__ uint2    g_KVc[NN * 32];  // {K_l2, V_l2*dis} (layer-2 weights)
__device__ float    g_dis[NN];
__device__ int      g_deg[NN];       // invariant: all-zero at kernel_launch entry
__device__ int      g_off[NN + 1];
__device__ int      g_cur[NN];
__device__ int4     g_csr4[(EE + 3) / 4 + 1];   // csr as int4 for aligned 16B uniform loads

__device__ __forceinline__ float2 u2f(unsigned u) {
    return __half22float2(*reinterpret_cast<const __half2*>(&u));
}
__device__ __forceinline__ unsigned f2u(float x, float y) {
    __half2 h = __floats2half2_rn(x, y);
    return *reinterpret_cast<unsigned*>(&h);
}

#define CP_ASYNC16(dst, src) \
    asm volatile("cp.async.cg.shared.global [%0], [%1], 16;" :: "r"(dst), "l"(src))
#define CP_COMMIT() asm volatile("cp.async.commit_group;")
#define CP_WAIT1()  asm volatile("cp.async.wait_group 1;")

// ---------------- CSR build ----------------
// single-block scan over NN elements; also computes dis, seeds cur, resets deg
__global__ void k_scan() {
    __shared__ int wsum[32];
    int t = threadIdx.x;
    int lane = t & 31, wid = t >> 5;
    int i0 = t * 25;
    int i1 = i0 + 25 < NN ? i0 + 25 : NN;
    int s = 0;
    for (int i = i0; i < i1; i++) s += g_deg[i] + 1;   // +1 = self loop
    int inc = s;
#pragma unroll
    for (int o = 1; o < 32; o <<= 1) {
        int v = __shfl_up_sync(0xffffffffu, inc, o);
        if (lane >= o) inc += v;
    }
    if (lane == 31) wsum[wid] = inc;
    __syncthreads();
    if (t < 32) {
        int v = wsum[t];
        int inc2 = v;
#pragma unroll
        for (int o = 1; o < 32; o <<= 1) {
            int u = __shfl_up_sync(0xffffffffu, inc2, o);
            if (t >= o) inc2 += u;
        }
        wsum[t] = inc2 - v;   // exclusive
    }
    __syncthreads();
    int run = wsum[wid] + (inc - s);
    for (int i = i0; i < i1; i++) {
        int d = g_deg[i] + 1;
        g_off[i] = run;
        g_cur[i] = run;
        g_dis[i] = rsqrtf((float)d);
        g_deg[i] = 0;          // restore invariant for next replay
        run += d;
    }
    if (t == 0) g_off[NN] = EE;
}

// scatter + in-place V1 scaling by dis (dis is ready; V1 was written by lin1)
__global__ void k_scatter(const int* __restrict__ ei) {
    int idx = blockIdx.x * blockDim.x + threadIdx.x;
    int stride = gridDim.x * blockDim.x;
    for (int i = idx; i < NN * 32; i += stride) {
        float d = g_dis[i >> 5];
        float2 f = u2f(g_V1[i]);
        g_V1[i] = f2u(f.x * d, f.y * d);
    }
    if (idx >= EE) return;
    int r, c;
    if (idx < NE) { r = ei[idx]; c = ei[NE + idx]; }
    else          { r = c = idx - NE; }               // self loop
    int p = atomicAdd(&g_cur[c], 1);
    ((int*)g_csr4)[p] = r;
}

// ---------------- helpers ----------------
__device__ __forceinline__ void gather_pair(float2 h, int g0, float (&xa)[8]) {
#pragma unroll
    for (int i = 0; i < 8; i += 2) {
        int src = g0 * 4 + (i >> 1);
        xa[i]     = __shfl_sync(0xffffffffu, h.x, src);
        xa[i + 1] = __shfl_sync(0xffffffffu, h.y, src);
    }
}

// conflict-free weight layout: float2 (g,i,op) -> smem[i*32 + g*4 + op]
// lane l = g*4+op, so glin reads sw[i*32 + lane]: lane-consecutive, zero conflicts
__device__ __forceinline__ void load_w_cf(const float* __restrict__ w, float2* sw) {
    for (int j = threadIdx.x; j < 256; j += blockDim.x) {
        int g = j >> 5, i = (j >> 2) & 7, op = j & 3;
        sw[i * 32 + g * 4 + op] = ((const float2*)w)[j];
    }
}

__device__ __forceinline__ float2 glin(const float2* sw, const float* sb,
                                       const float (&xa)[8], int lane) {
    float2 o = ((const float2*)sb)[lane];
#pragma unroll
    for (int i = 0; i < 8; i++) {
        float2 w = sw[i * 32 + lane];
        o.x += xa[i] * w.x;
        o.y += xa[i] * w.y;
    }
    return o;
}

// ---------------- fused edge-histogram + lin1 (cp.async, 16 nodes/warp) + qkv1 ----------------
// block = 128 thr = 4 warps, 64 nodes/block (16 per warp); lane = out pair {2l,2l+1}
__global__ void k_lin1histqkv1(const float* __restrict__ x, const float* __restrict__ w,
                               const float* __restrict__ b,
                               const float* __restrict__ wv0, const float* __restrict__ bv0,
                               const int* __restrict__ ei) {
    __shared__ float4 sx[2][64][16];   // double buffer: 2 x 64 nodes x 64 k (16 float4)
    __shared__ float2 swv[256];
    __shared__ float sbv[64];
    int t = threadIdx.x;

    // edge histogram (independent work; atomics drain during the GEMM below)
    {
        int stride = gridDim.x * blockDim.x;
        for (int e = blockIdx.x * blockDim.x + t; e < NE; e += stride)
            atomicAdd(&g_deg[ei[NE + e]], 1);
    }

    load_w_cf(wv0, swv);
    if (t < 64) sbv[t] = bv0[t];
    int warp = t >> 5, lane = t & 31;
    int nodeBase = blockIdx.x * 64;
    const float4* __restrict__ X4 = (const float4*)x;
    const float2* __restrict__ W2 = (const float2*)w;

    // staging geometry: 2 threads per row, 8 consecutive float4 per thread
    int srow = t >> 1;
    int scol = (t & 1) * 8;
    int node_s = nodeBase + srow;
    const float4* __restrict__ Xs = X4 + (size_t)node_s * 64 + scol;
    bool ld_ok = (node_s < NN);

#pragma unroll
    for (int tl = 0; tl < 2; tl++) {
        if (ld_ok) {
#pragma unroll
            for (int i = 0; i < 8; i++) {
                unsigned dst = (unsigned)__cvta_generic_to_shared(&sx[tl][srow][scol + i]);
                CP_ASYNC16(dst, Xs + tl * 16 + i);
            }
        }
        CP_COMMIT();
    }

    float2 acc[16];
#pragma unroll
    for (int n = 0; n < 16; n++) acc[n] = make_float2(0.f, 0.f);

#pragma unroll
    for (int tile = 0; tile < 4; tile++) {
        CP_WAIT1();
        __syncthreads();
        int buf = tile & 1;
        int k0 = tile * 64;
#pragma unroll 2
        for (int ks = 0; ks < 16; ks++) {
            int kw = (k0 + ks * 4) * 32 + lane;
            float2 w0 = W2[kw];
            float2 w1 = W2[kw + 32];
            float2 w2v = W2[kw + 64];
            float2 w3 = W2[kw + 96];
#pragma unroll
            for (int n = 0; n < 16; n++) {
                float4 xv = sx[buf][warp * 16 + n][ks];
                acc[n].x = fmaf(xv.x, w0.x, fmaf(xv.y, w1.x,
                           fmaf(xv.z, w2v.x, fmaf(xv.w, w3.x, acc[n].x))));
                acc[n].y = fmaf(xv.x, w0.y, fmaf(xv.y, w1.y,
                           fmaf(xv.z, w2v.y, fmaf(xv.w, w3.y, acc[n].y))));
            }
        }
        __syncthreads();
        if (tile + 2 < 4 && ld_ok) {
#pragma unroll
            for (int i = 0; i < 8; i++) {
                unsigned dst = (unsigned)__cvta_generic_to_shared(&sx[buf][srow][scol + i]);
                CP_ASYNC16(dst, Xs + (tile + 2) * 16 + i);
            }
        }
        CP_COMMIT();
    }

    float2 bb = ((const float2*)b)[lane];
    int g0 = lane >> 2;
#pragma unroll
    for (int n = 0; n < 16; n++) {
        int node = nodeBase + warp * 16 + n;
        float2 h = make_float2(fmaxf(acc[n].x + bb.x, 0.f), fmaxf(acc[n].y + bb.y, 0.f));
        float xa[8];
        gather_pair(h, g0, xa);           // all lanes participate (no divergence)
        float2 vv = glin(swv, sbv, xa, lane);
        if (node < NN) {
            g_x0[node * 32 + lane] = h;
            g_V1[node * 32 + lane] = f2u(vv.x, vv.y);   // unscaled; k_scatter applies dis
        }
    }
}

// ---------------- fused edge1 (identity attention) + qkv2 ----------------
__global__ void k_edge1qkv2(const float* __restrict__ wq, const float* __restrict__ bq,
                            const float* __restrict__ wk, const float* __restrict__ bk,
                            const float* __restrict__ wv, const float* __restrict__ bv) {
    __shared__ float2 swq[256], swk[256], swv[256];
    __shared__ float sbq[64], sbk[64], sbv[64];
    load_w_cf(wq, swq);
    load_w_cf(wk, swk);
    load_w_cf(wv, swv);
    if (threadIdx.x < 64) {
        sbq[threadIdx.x] = bq[threadIdx.x];
        sbk[threadIdx.x] = bk[threadIdx.x];
        sbv[threadIdx.x] = bv[threadIdx.x];
    }
    __syncthreads();
    int c = (blockIdx.x * blockDim.x + threadIdx.x) >> 5;
    if (c >= NN) return;
    int lane = threadIdx.x & 31;
    float ax = 0.f, ay = 0.f;
    int j = g_off[c], end = g_off[c + 1];
    const unsigned* __restrict__ V1 = g_V1;
    const int* __restrict__ csr = (const int*)g_csr4;
    // align j to 4 for int4 batches
    for (; j < end && (j & 3); j++) {
        float2 f = u2f(V1[csr[j] * 32 + lane]);
        ax += f.x;  ay += f.y;
    }
    // 8-wide batches (2 uniform int4 loads, 8 gathers in flight)
    for (; j + 8 <= end; j += 8) {
        int4 ra = g_csr4[j >> 2];
        int4 rb = g_csr4[(j >> 2) + 1];
        unsigned u0 = V1[ra.x * 32 + lane];
        unsigned u1 = V1[ra.y * 32 + lane];
        unsigned u2 = V1[ra.z * 32 + lane];
        unsigned u3 = V1[ra.w * 32 + lane];
        unsigned u4 = V1[rb.x * 32 + lane];
        unsigned u5 = V1[rb.y * 32 + lane];
        unsigned u6 = V1[rb.z * 32 + lane];
        unsigned u7 = V1[rb.w * 32 + lane];
        float2 f0 = u2f(u0), f1 = u2f(u1), f2 = u2f(u2), f3 = u2f(u3);
        float2 f4 = u2f(u4), f5 = u2f(u5), f6 = u2f(u6), f7 = u2f(u7);
        ax += ((f0.x + f1.x) + (f2.x + f3.x)) + ((f4.x + f5.x) + (f6.x + f7.x));
        ay += ((f0.y + f1.y) + (f2.y + f3.y)) + ((f4.y + f5.y) + (f6.y + f7.y));
    }
    if (j + 4 <= end) {
        int4 rr = g_csr4[j >> 2];
        unsigned u0 = V1[rr.x * 32 + lane];
        unsigned u1 = V1[rr.y * 32 + lane];
        unsigned u2 = V1[rr.z * 32 + lane];
        unsigned u3 = V1[rr.w * 32 + lane];
        float2 f0 = u2f(u0), f1 = u2f(u1), f2 = u2f(u2), f3 = u2f(u3);
        ax += (f0.x + f1.x) + (f2.x + f3.x);
        ay += (f0.y + f1.y) + (f2.y + f3.y);
        j += 4;
    }
    for (; j < end; j++) {
        float2 f = u2f(V1[csr[j] * 32 + lane]);
        ax += f.x;  ay += f.y;
    }
    float dc = g_dis[c];
    float2 h1 = make_float2(fmaxf(ax * dc, 0.f), fmaxf(ay * dc, 0.f));
    g_x1[c * 32 + lane] = h1;

    // qkv2: layers {0,1} K,V + Q(layer1), with net-layer-1 weights
    int g0 = lane >> 2;
    float2 h0 = g_x0[c * 32 + lane];
    float xa[8];
    uint4 pack;
    gather_pair(h0, g0, xa);
    {
        float2 kk = glin(swk, sbk, xa, lane);
        float2 vv = glin(swv, sbv, xa, lane);
        pack.x = f2u(kk.x, kk.y);
        pack.y = f2u(vv.x * dc, vv.y * dc);
    }
    gather_pair(h1, g0, xa);
    {
        float2 kk = glin(swk, sbk, xa, lane);
        float2 vv = glin(swv, sbv, xa, lane);
        float2 qq = glin(swq, sbq, xa, lane);
        pack.z = f2u(kk.x, kk.y);
        pack.w = f2u(vv.x * dc, vv.y * dc);
        g_QA[c * 32 + lane] = make_float2(qq.x * SC, qq.y * SC);
    }
    g_KVA[c * 32 + lane] = pack;
}

// ---------------- attention accumulators ----------------
__device__ __forceinline__ void acc2(uint4 d, float2 qv, float& ax, float& ay) {
    float2 k0 = u2f(d.x), v0 = u2f(d.y), k1 = u2f(d.z), v1 = u2f(d.w);
    float s0 = qv.x * k0.x + qv.y * k0.y;
    s0 += __shfl_xor_sync(0xffffffffu, s0, 1);
    s0 += __shfl_xor_sync(0xffffffffu, s0, 2);
    float s1 = qv.x * k1.x + qv.y * k1.y;
    s1 += __shfl_xor_sync(0xffffffffu, s1, 1);
    s1 += __shfl_xor_sync(0xffffffffu, s1, 2);
    float m = fmaxf(s0, s1);
    float e0 = __expf(s0 - m), e1 = __expf(s1 - m);
    float inv = __fdividef(1.0f, e0 + e1);
    ax += (e0 * v0.x + e1 * v1.x) * inv;
    ay += (e0 * v0.y + e1 * v1.y) * inv;
}

__device__ __forceinline__ void acc3(uint4 d, uint2 e, float2 qv, float& ax, float& ay) {
    float2 k0 = u2f(d.x), v0 = u2f(d.y), k1 = u2f(d.z), v1 = u2f(d.w);
    float2 k2 = u2f(e.x), v2 = u2f(e.y);
    float s0 = qv.x * k0.x + qv.y * k0.y;
    s0 += __shfl_xor_sync(0xffffffffu, s0, 1);
    s0 += __shfl_xor_sync(0xffffffffu, s0, 2);
    float s1 = qv.x * k1.x + qv.y * k1.y;
    s1 += __shfl_xor_sync(0xffffffffu, s1, 1);
    s1 += __shfl_xor_sync(0xffffffffu, s1, 2);
    float s2 = qv.x * k2.x + qv.y * k2.y;
    s2 += __shfl_xor_sync(0xffffffffu, s2, 1);
    s2 += __shfl_xor_sync(0xffffffffu, s2, 2);
    float m = fmaxf(fmaxf(s0, s1), s2);
    float e0 = __expf(s0 - m), e1 = __expf(s1 - m), e2 = __expf(s2 - m);
    float inv = __fdividef(1.0f, e0 + e1 + e2);
    ax += (e0 * v0.x + e1 * v1.x + e2 * v2.x) * inv;
    ay += (e0 * v0.y + e1 * v1.y + e2 * v2.y) * inv;
}

// ---------------- fused edge2 + qkv3 ----------------
__global__ void k_edge2qkv3(const float* __restrict__ wq, const float* __restrict__ bq,
                            const float* __restrict__ wk, const float* __restrict__ bk,
                            const float* __restrict__ wv, const float* __restrict__ bv) {
    __shared__ float2 swq[256], swk[256], swv[256];
    __shared__ float sbq[64], sbk[64], sbv[64];
    load_w_cf(wq, swq);
    load_w_cf(wk, swk);
    load_w_cf(wv, swv);
    if (threadIdx.x < 64) {
        sbq[threadIdx.x] = bq[threadIdx.x];
        sbk[threadIdx.x] = bk[threadIdx.x];
        sbv[threadIdx.x] = bv[threadIdx.x];
    }
    __syncthreads();
    int c = (blockIdx.x * blockDim.x + threadIdx.x) >> 5;
    if (c >= NN) return;
    int lane = threadIdx.x & 31;
    float2 qv = g_QA[c * 32 + lane];
    float ax = 0.f, ay = 0.f;
    int j = g_off[c], end = g_off[c + 1];
    const uint4* __restrict__ KV = g_KVA;
    const int* __restrict__ csr = (const int*)g_csr4;
    for (; j < end && (j & 3); j++)
        acc2(KV[csr[j] * 32 + lane], qv, ax, ay);
    for (; j + 4 <= end; j += 4) {
        int4 rr = g_csr4[j >> 2];
        uint4 d0 = KV[rr.x * 32 + lane];
        uint4 d1 = KV[rr.y * 32 + lane];
        uint4 d2 = KV[rr.z * 32 + lane];
        uint4 d3 = KV[rr.w * 32 + lane];
        acc2(d0, qv, ax, ay);
        acc2(d1, qv, ax, ay);
        acc2(d2, qv, ax, ay);
        acc2(d3, qv, ax, ay);
    }
    for (; j < end; j++)
        acc2(KV[csr[j] * 32 + lane], qv, ax, ay);

    float dc = g_dis[c];
    float2 h2 = make_float2(fmaxf(ax * dc, 0.f), fmaxf(ay * dc, 0.f));

    // qkv3: layers {0,1,2} K,V + Q(layer2), with net-layer-2 weights
    int g0 = lane >> 2;
    float xa[8];
    uint4 packA;
    gather_pair(g_x0[c * 32 + lane], g0, xa);
    {
        float2 kk = glin(swk, sbk, xa, lane);
        float2 vv = glin(swv, sbv, xa, lane);
        packA.x = f2u(kk.x, kk.y);
        packA.y = f2u(vv.x * dc, vv.y * dc);
    }
    gather_pair(g_x1[c * 32 + lane], g0, xa);
    {
        float2 kk = glin(swk, sbk, xa, lane);
        float2 vv = glin(swv, sbv, xa, lane);
        packA.z = f2u(kk.x, kk.y);
        packA.w = f2u(vv.x * dc, vv.y * dc);
    }
    g_KVB[c * 32 + lane] = packA;
    gather_pair(h2, g0, xa);
    {
        float2 kk = glin(swk, sbk, xa, lane);
        float2 vv = glin(swv, sbv, xa, lane);
        float2 qq = glin(swq, sbq, xa, lane);
        g_KVc[c * 32 + lane] = make_uint2(f2u(kk.x, kk.y), f2u(vv.x * dc, vv.y * dc));
        g_QB[c * 32 + lane] = make_float2(qq.x * SC, qq.y * SC);
    }
}

// ---------------- fused edge3 + lin2 + log_softmax ----------------
__global__ void k_edge3lin2(const float* __restrict__ w, const float* __restrict__ b,
                            float* __restrict__ out) {
    __shared__ float sw[2048];   // [64][32]
    __shared__ float sb[32];
    for (int i = threadIdx.x; i < 2048; i += blockDim.x) sw[i] = w[i];
    if (threadIdx.x < 32) sb[threadIdx.x] = b[threadIdx.x];
    __syncthreads();
    int c = (blockIdx.x * blockDim.x + threadIdx.x) >> 5;
    if (c >= NN) return;
    int lane = threadIdx.x & 31;
    float2 qv = g_QB[c * 32 + lane];
    float ax = 0.f, ay = 0.f;
    int j = g_off[c], end = g_off[c + 1];
    const uint4* __restrict__ KVa = g_KVB;
    const uint2* __restrict__ KVc = g_KVc;
    const int* __restrict__ csr = (const int*)g_csr4;
    for (; j < end && (j & 3); j++) {
        int r = csr[j];
        acc3(KVa[r * 32 + lane], KVc[r * 32 + lane], qv, ax, ay);
    }
    for (; j + 4 <= end; j += 4) {
        int4 rr = g_csr4[j >> 2];
        uint4 d0 = KVa[rr.x * 32 + lane];
        uint4 d1 = KVa[rr.y * 32 + lane];
        uint4 d2 = KVa[rr.z * 32 + lane];
        uint4 d3 = KVa[rr.w * 32 + lane];
        uint2 e0 = KVc[rr.x * 32 + lane];
        uint2 e1 = KVc[rr.y * 32 + lane];
        uint2 e2 = KVc[rr.z * 32 + lane];
        uint2 e3 = KVc[rr.w * 32 + lane];
        acc3(d0, e0, qv, ax, ay);
        acc3(d1, e1, qv, ax, ay);
        acc3(d2, e2, qv, ax, ay);
        acc3(d3, e3, qv, ax, ay);
    }
    for (; j < end; j++) {
        int r = csr[j];
        acc3(KVa[r * 32 + lane], KVc[r * 32 + lane], qv, ax, ay);
    }
    float dc = g_dis[c];
    float hx = fmaxf(ax * dc, 0.f), hy = fmaxf(ay * dc, 0.f);

    // lin2: lane = class; h dims {2lp, 2lp+1} live in lane lp
    float acc = sb[lane];
#pragma unroll
    for (int lp = 0; lp < 32; lp++) {
        float bx = __shfl_sync(0xffffffffu, hx, lp);
        float by = __shfl_sync(0xffffffffu, hy, lp);
        acc += bx * sw[(2 * lp) * 32 + lane] + by * sw[(2 * lp + 1) * 32 + lane];
    }
    float m = acc;
#pragma unroll
    for (int o = 16; o; o >>= 1) m = fmaxf(m, __shfl_xor_sync(0xffffffffu, m, o));
    float e = __expf(acc - m);
    float sum = e;
#pragma unroll
    for (int o = 16; o; o >>= 1) sum += __shfl_xor_sync(0xffffffffu, sum, o);
    out[(size_t)c * 32 + lane] = acc - m - logf(sum);
}

// ---------------- launch ----------------
extern "C" void kernel_launch(void* const* d_in, const int* in_sizes, int n_in,
                              void* d_out, int out_size) {
    const float* x  = (const float*)d_in[0];
    const int*   ei = (const int*)d_in[1];
    const float* w1 = (const float*)d_in[2];
    const float* b1 = (const float*)d_in[3];
    const float* wq = (const float*)d_in[4];
    const float* bq = (const float*)d_in[5];
    const float* wk = (const float*)d_in[6];
    const float* bk = (const float*)d_in[7];
    const float* wv = (const float*)d_in[8];
    const float* bv = (const float*)d_in[9];
    const float* w2 = (const float*)d_in[10];
    const float* b2 = (const float*)d_in[11];
    float* out = (float*)d_out;

    const int gridW = (NN * 32 + 255) / 256;   // warp-per-node kernels
    const int gridT = (NN + 63) / 64;          // 64 nodes per block for lin1 (128 thr)

    // launch 0: encoder + layer-0 V + edge histogram (fused, 16 nodes/warp)
    k_lin1histqkv1<<<gridT, 128>>>(x, w1, b1, wv, bv, ei);
    // launch 1: CSR offsets (+dis)
    k_scan<<<1, 1024>>>();
    // launch 2: scatter + V1 *= dis
    k_scatter<<<(EE + 255) / 256, 256>>>(ei);

    // launch 3: layer-0 edge + qkv for layer 1   <- 4th launch: ncu target
    k_edge1qkv2<<<gridW, 256>>>(wq + 512, bq + 64, wk + 512, bk + 64, wv + 512, bv + 64);
    // launch 4: layer-1 edge + qkv for layer 2
    k_edge2qkv3<<<gridW, 256>>>(wq + 1024, bq + 128, wk + 1024, bk + 128, wv + 1024, bv + 128);
    // launch 5: layer-2 edge + classifier
    k_edge3lin2<<<gridW, 256>>>(w2, b2, out);
}